// round 9
// baseline (speedup 1.0000x reference)
#include <cuda_runtime.h>
#include <cuda_bf16.h>
#include <cstdint>

#define N_TOK 98
#define DIM   128
#define HEADS 4
#define NWIN  64
#define SCALE 0.17677669529663687f

#define MAX_B    2048
#define MAX_MTOT (MAX_B * N_TOK)

// pre-split operands (bf16 hi/lo)
__device__ __nv_bfloat16 g_xh[(size_t)MAX_MTOT * 128];
__device__ __nv_bfloat16 g_xl[(size_t)MAX_MTOT * 128];
__device__ __nv_bfloat16 g_qwh[384 * 128];
__device__ __nv_bfloat16 g_qwl[384 * 128];
__device__ __nv_bfloat16 g_pwh[128 * 128];
__device__ __nv_bfloat16 g_pwl[128 * 128];
__device__ __nv_bfloat16 g_qkvh[(size_t)MAX_MTOT * 384];
__device__ __nv_bfloat16 g_qkvl[(size_t)MAX_MTOT * 384];
__device__ __nv_bfloat16 g_oh[(size_t)MAX_MTOT * 128];
__device__ __nv_bfloat16 g_ol[(size_t)MAX_MTOT * 128];
__device__ float g_comb[NWIN * HEADS * N_TOK * N_TOK];

// ======================= helpers =======================
static __device__ __forceinline__ uint32_t smem_u32(const void* p) {
    uint32_t a;
    asm("{ .reg .u64 t; cvta.to.shared.u64 t, %1; cvt.u32.u64 %0, t; }" : "=r"(a) : "l"(p));
    return a;
}
#define LDSM_X4(r0, r1, r2, r3, addr)                                          \
    asm volatile("ldmatrix.sync.aligned.m8n8.x4.shared.b16 {%0,%1,%2,%3}, [%4];" \
                 : "=r"(r0), "=r"(r1), "=r"(r2), "=r"(r3) : "r"(addr))
#define LDSM_X4_T(r0, r1, r2, r3, addr)                                        \
    asm volatile("ldmatrix.sync.aligned.m8n8.x4.trans.shared.b16 {%0,%1,%2,%3}, [%4];" \
                 : "=r"(r0), "=r"(r1), "=r"(r2), "=r"(r3) : "r"(addr))
#define MMA_BF16(c, a, b0, b1)                                                 \
    asm volatile("mma.sync.aligned.m16n8k16.row.col.f32.bf16.bf16.f32 "        \
                 "{%0,%1,%2,%3}, {%4,%5,%6,%7}, {%8,%9}, {%0,%1,%2,%3};"       \
                 : "+f"((c)[0]), "+f"((c)[1]), "+f"((c)[2]), "+f"((c)[3])      \
                 : "r"((a)[0]), "r"((a)[1]), "r"((a)[2]), "r"((a)[3]),         \
                   "r"(b0), "r"(b1))
#define CP_ASYNC16(dst, src, sz)                                               \
    asm volatile("cp.async.cg.shared.global [%0], [%1], 16, %2;"               \
                 :: "r"(dst), "l"(src), "r"(sz))
#define CP_COMMIT() asm volatile("cp.async.commit_group;" ::: "memory")
#define CP_WAIT1()  asm volatile("cp.async.wait_group 1;" ::: "memory")
#define CP_WAIT0()  asm volatile("cp.async.wait_group 0;" ::: "memory")

static __device__ __forceinline__ void bf16split(float a, __nv_bfloat16& h, __nv_bfloat16& l) {
    h = __float2bfloat16_rn(a);
    l = __float2bfloat16_rn(a - __bfloat162float(h));
}
static __device__ __forceinline__ uint32_t pack_split(float a, float b, uint32_t& lo) {
    __nv_bfloat16 ah, al, bh, bl;
    bf16split(a, ah, al); bf16split(b, bh, bl);
    uint16_t ahu = *(uint16_t*)&ah, alu = *(uint16_t*)&al;
    uint16_t bhu = *(uint16_t*)&bh, blu = *(uint16_t*)&bl;
    lo = ((uint32_t)blu << 16) | alu;
    return ((uint32_t)bhu << 16) | ahu;
}

extern __shared__ char smraw[];

// ======================= split prologue =======================
__global__ void split_kernel(const float* __restrict__ src,
                             __nv_bfloat16* __restrict__ h,
                             __nv_bfloat16* __restrict__ l, int n8)
{
    int i = blockIdx.x * 256 + threadIdx.x;
    if (i >= n8) return;
    const float4* s = (const float4*)src;
    float4 a = s[i * 2], b = s[i * 2 + 1];
    __nv_bfloat16 hh[8], ll[8];
    bf16split(a.x, hh[0], ll[0]); bf16split(a.y, hh[1], ll[1]);
    bf16split(a.z, hh[2], ll[2]); bf16split(a.w, hh[3], ll[3]);
    bf16split(b.x, hh[4], ll[4]); bf16split(b.y, hh[5], ll[5]);
    bf16split(b.z, hh[6], ll[6]); bf16split(b.w, hh[7], ll[7]);
    *(uint4*)&h[(size_t)i * 8] = *(uint4*)hh;
    *(uint4*)&l[(size_t)i * 8] = *(uint4*)ll;
}

// ======================= bf16x3 GEMM (pre-split operands, cp.async) =======================
// smem: A hi/lo [128][136]; W 2 buffers of [128][40] hi/lo (K-32 chunks)
#define AHI_  0
#define ALO_  34816
#define WB0H  69632
#define WB1H  90112
#define G_SMEM_BYTES 110592

template <int MODE>   // 0 = QKV (split bf16 out, scale y==0), 1 = proj (fp32 out)
__global__ __launch_bounds__(256, 2)
void gemm_bf16x3(const __nv_bfloat16* __restrict__ Ah,
                 const __nv_bfloat16* __restrict__ Al,
                 const __nv_bfloat16* __restrict__ Wh,
                 const __nv_bfloat16* __restrict__ Wl,
                 const float* __restrict__ bias,
                 __nv_bfloat16* __restrict__ OutH,
                 __nv_bfloat16* __restrict__ OutL,
                 float* __restrict__ OutF,
                 int Nout, int Mtot)
{
    const uint32_t sbase = smem_u32(smraw);
    const int tid  = threadIdx.x;
    const int lane = tid & 31;
    const int warp = tid >> 5;
    const int wm   = warp & 3;
    const int wn   = warp >> 2;
    const long row0 = (long)blockIdx.x * 128;
    const int  col0 = blockIdx.y * 128;

    // ---- A staging via cp.async (group together with W chunk 0) ----
#pragma unroll
    for (int jj = 0; jj < 16; jj++) {
        int lin = tid + jj * 256;             // 4096
        int arr = lin >> 11, rem = lin & 2047;
        int r = rem >> 4, cc = rem & 15;
        long row = row0 + r;
        int  sz  = (row < Mtot) ? 16 : 0;
        long rsrc = (row < Mtot) ? row : 0;
        const __nv_bfloat16* s = (arr ? Al : Ah) + rsrc * 128 + cc * 8;
        uint32_t d = sbase + (arr ? ALO_ : AHI_) + (uint32_t)(r * 272 + cc * 16);
        CP_ASYNC16(d, s, sz);
    }
    // ---- W chunk staging helper ----
    auto stage_w = [&](int kc, int bufsel) {
        uint32_t dh = sbase + (bufsel ? WB1H : WB0H);
#pragma unroll
        for (int jj = 0; jj < 4; jj++) {
            int lin = tid + jj * 256;         // 1024
            int arr = lin >> 9, rem = lin & 511;
            int r = rem >> 2, cc = rem & 3;
            const __nv_bfloat16* s = (arr ? Wl : Wh) + (size_t)(col0 + r) * 128 + kc * 32 + cc * 8;
            uint32_t d = dh + (arr ? 10240u : 0u) + (uint32_t)(r * 80 + cc * 16);
            CP_ASYNC16(d, s, 16);
        }
    };
    stage_w(0, 0); CP_COMMIT();
    stage_w(1, 1); CP_COMMIT();

    float acc[2][8][4];
#pragma unroll
    for (int mt = 0; mt < 2; mt++)
#pragma unroll
        for (int nt = 0; nt < 8; nt++)
#pragma unroll
            for (int i = 0; i < 4; i++) acc[mt][nt][i] = 0.f;

    const int a_row = wm * 32 + (lane & 15);
    const int a_cs  = (lane >> 4) * 8;
    const int b_i   = lane >> 3;
    const int b_rp  = (b_i >> 1) * 8 + (lane & 7);
    const int b_cs  = (b_i & 1) * 8;

#pragma unroll 1
    for (int kc = 0; kc < 4; kc++) {
        if (kc < 3) CP_WAIT1(); else CP_WAIT0();
        __syncthreads();
        uint32_t bh_base = sbase + ((kc & 1) ? WB1H : WB0H);
        uint32_t bl_base = bh_base + 10240;
#pragma unroll
        for (int ks = 0; ks < 2; ks++) {
            uint32_t ah[2][4], al[2][4];
#pragma unroll
            for (int mt = 0; mt < 2; mt++) {
                uint32_t off = (uint32_t)((a_row + mt * 16) * 272 + (kc * 32 + ks * 16 + a_cs) * 2);
                LDSM_X4(ah[mt][0], ah[mt][1], ah[mt][2], ah[mt][3], sbase + AHI_ + off);
                LDSM_X4(al[mt][0], al[mt][1], al[mt][2], al[mt][3], sbase + ALO_ + off);
            }
#pragma unroll
            for (int np = 0; np < 4; np++) {
                uint32_t off = (uint32_t)((wn * 64 + np * 16 + b_rp) * 80 + (ks * 16 + b_cs) * 2);
                uint32_t h0, h1, h2, h3, l0, l1, l2, l3;
                LDSM_X4(h0, h1, h2, h3, bh_base + off);
                LDSM_X4(l0, l1, l2, l3, bl_base + off);
#pragma unroll
                for (int mt = 0; mt < 2; mt++) {
                    MMA_BF16(acc[mt][np * 2],     ah[mt], h0, h1);
                    MMA_BF16(acc[mt][np * 2],     al[mt], h0, h1);
                    MMA_BF16(acc[mt][np * 2],     ah[mt], l0, l1);
                    MMA_BF16(acc[mt][np * 2 + 1], ah[mt], h2, h3);
                    MMA_BF16(acc[mt][np * 2 + 1], al[mt], h2, h3);
                    MMA_BF16(acc[mt][np * 2 + 1], ah[mt], l2, l3);
                }
            }
        }
        __syncthreads();
        if (kc + 2 <= 3) { stage_w(kc + 2, kc & 1); CP_COMMIT(); }
    }

    // ---- epilogue ----
    const int er = lane >> 2;
    const int ec = (lane & 3) * 2;
    const float osc = (MODE == 0 && blockIdx.y == 0) ? SCALE : 1.f;
#pragma unroll
    for (int mt = 0; mt < 2; mt++) {
        long r = row0 + wm * 32 + mt * 16 + er;
#pragma unroll
        for (int nt = 0; nt < 8; nt++) {
            int c = col0 + wn * 64 + nt * 8 + ec;
            float b0 = bias[c], b1 = bias[c + 1];
            if (MODE == 0) {
                if (r < Mtot) {
                    uint32_t ul, uh = pack_split((acc[mt][nt][0] + b0) * osc,
                                                 (acc[mt][nt][1] + b1) * osc, ul);
                    *(uint32_t*)&OutH[r * Nout + c] = uh;
                    *(uint32_t*)&OutL[r * Nout + c] = ul;
                }
                if (r + 8 < Mtot) {
                    uint32_t ul, uh = pack_split((acc[mt][nt][2] + b0) * osc,
                                                 (acc[mt][nt][3] + b1) * osc, ul);
                    *(uint32_t*)&OutH[(r + 8) * Nout + c] = uh;
                    *(uint32_t*)&OutL[(r + 8) * Nout + c] = ul;
                }
            } else {
                if (r < Mtot)
                    *(float2*)&OutF[r * Nout + c] =
                        make_float2(acc[mt][nt][0] + b0, acc[mt][nt][1] + b1);
                if (r + 8 < Mtot)
                    *(float2*)&OutF[(r + 8) * Nout + c] =
                        make_float2(acc[mt][nt][2] + b0, acc[mt][nt][3] + b1);
            }
        }
    }
}

// ======================= comb = bias_table[rel_idx] + mask =======================
__global__ void comb_kernel(const float* __restrict__ mask,
                            const float* __restrict__ bias_table,
                            const int*   __restrict__ rel_idx)
{
    int idx = blockIdx.x * blockDim.x + threadIdx.x;
    const int total = NWIN * HEADS * N_TOK * N_TOK;
    if (idx >= total) return;
    int w   = idx / (HEADS * N_TOK * N_TOK);
    int rem = idx - w * (HEADS * N_TOK * N_TOK);
    int h   = rem / (N_TOK * N_TOK);
    int nm  = rem - h * (N_TOK * N_TOK);
    g_comb[idx] = bias_table[rel_idx[nm] * HEADS + h] + mask[w * (N_TOK * N_TOK) + nm];
}

// ======================= attention v5: pre-split staging, register flash =======================
#define TQH 0
#define TQL 30464
#define TKH 60928
#define TKL 91392
#define TVH 121856
#define TVL 152320
#define ATTN_SMEM 182784

__global__ __launch_bounds__(512, 1)
void attn_kernel()
{
    char* sb = smraw;
    const uint32_t sbase = smem_u32(sb);
    const int b    = blockIdx.x;
    const int tid  = threadIdx.x;
    const int lane = tid & 31;
    const int warp = tid >> 5;
    const int win  = b & (NWIN - 1);

    // zero V pad rows 98..111 (hi/lo)
    for (int i = tid; i < 14 * 68; i += 512) {
        int r = 98 + i / 68, c4 = (i % 68) * 2;
        *(uint32_t*)(sb + TVH + (r * 136 + c4) * 2) = 0u;
        *(uint32_t*)(sb + TVL + (r * 136 + c4) * 2) = 0u;
    }

    // ---- stage Q/K/V hi/lo: pure copies (split + scale already done upstream) ----
    {
        const __nv_bfloat16* qh = g_qkvh + (size_t)b * N_TOK * 384;
        const __nv_bfloat16* ql = g_qkvl + (size_t)b * N_TOK * 384;
        for (int i = tid; i < N_TOK * 32; i += 512) {
            int m = i >> 5, c = (i & 31) * 4;
            int so = m * 384 + c;
            int dq = (m * 136 + c) * 2;
            *(uint2*)(sb + TQH + dq) = *(const uint2*)&qh[so];
            *(uint2*)(sb + TQL + dq) = *(const uint2*)&ql[so];
            *(uint2*)(sb + TKH + dq) = *(const uint2*)&qh[so + 128];
            *(uint2*)(sb + TKL + dq) = *(const uint2*)&ql[so + 128];
            *(uint2*)(sb + TVH + dq) = *(const uint2*)&qh[so + 256];
            *(uint2*)(sb + TVL + dq) = *(const uint2*)&ql[so + 256];
        }
    }
    __syncthreads();

    const int a_rp = lane & 15;
    const int a_cs = (lane >> 4) * 8;
    const int b_i  = lane >> 3;
    const int b_rp = (b_i >> 1) * 8 + (lane & 7);
    const int b_cs = (b_i & 1) * 8;
    const int t_rp = (b_i & 1) * 8 + (lane & 7);
    const int t_cs = (b_i >> 1) * 8;
    const int er   = lane >> 2;
    const int ec   = (lane & 3) * 2;

#pragma unroll 1
    for (int item = warp; item < 28; item += 16) {
        const int h  = item / 7;
        const int mt = item - h * 7;

        // ---- QK^T ----
        float acc[14][4];
#pragma unroll
        for (int nt = 0; nt < 14; nt++)
#pragma unroll
            for (int i = 0; i < 4; i++) acc[nt][i] = 0.f;

#pragma unroll
        for (int ks = 0; ks < 2; ks++) {
            const int kb = h * 32 + ks * 16;
            uint32_t ah[4], al[4];
            uint32_t aoff = (uint32_t)((mt * 16 + a_rp) * 136 + kb + a_cs) * 2;
            LDSM_X4(ah[0], ah[1], ah[2], ah[3], sbase + TQH + aoff);
            LDSM_X4(al[0], al[1], al[2], al[3], sbase + TQL + aoff);
#pragma unroll
            for (int np = 0; np < 7; np++) {
                uint32_t boff = (uint32_t)((np * 16 + b_rp) * 136 + kb + b_cs) * 2;
                uint32_t h0, h1, h2, h3, l0, l1, l2, l3;
                LDSM_X4(h0, h1, h2, h3, sbase + TKH + boff);
                LDSM_X4(l0, l1, l2, l3, sbase + TKL + boff);
                MMA_BF16(acc[np * 2],     ah, h0, h1);
                MMA_BF16(acc[np * 2],     al, h0, h1);
                MMA_BF16(acc[np * 2],     ah, l0, l1);
                MMA_BF16(acc[np * 2 + 1], ah, h2, h3);
                MMA_BF16(acc[np * 2 + 1], al, h2, h3);
                MMA_BF16(acc[np * 2 + 1], ah, l2, l3);
            }
        }

        // ---- softmax in registers ----
        const float* combh = g_comb + (size_t)(win * HEADS + h) * N_TOK * N_TOK;
#pragma unroll
        for (int rr = 0; rr < 2; rr++) {
            int n = mt * 16 + er + rr * 8;
            bool rowok = (n < N_TOK);
            int  nc = rowok ? n : 0;
            float mx = -1e30f;
#pragma unroll
            for (int nt = 0; nt < 14; nt++) {
                int m = nt * 8 + ec;
                float v0 = -1e30f, v1 = -1e30f;
                if (m < N_TOK) {
                    float2 cb = *(const float2*)&combh[nc * N_TOK + m];
                    v0 = acc[nt][rr * 2]     + cb.x;
                    v1 = acc[nt][rr * 2 + 1] + cb.y;
                }
                acc[nt][rr * 2] = v0; acc[nt][rr * 2 + 1] = v1;
                mx = fmaxf(mx, fmaxf(v0, v1));
            }
            mx = fmaxf(mx, __shfl_xor_sync(0xffffffffu, mx, 1));
            mx = fmaxf(mx, __shfl_xor_sync(0xffffffffu, mx, 2));
            float sum = 0.f;
#pragma unroll
            for (int nt = 0; nt < 14; nt++) {
                float e0 = __expf(acc[nt][rr * 2]     - mx);
                float e1 = __expf(acc[nt][rr * 2 + 1] - mx);
                acc[nt][rr * 2] = e0; acc[nt][rr * 2 + 1] = e1;
                sum += e0 + e1;
            }
            sum += __shfl_xor_sync(0xffffffffu, sum, 1);
            sum += __shfl_xor_sync(0xffffffffu, sum, 2);
            float inv = rowok ? __fdividef(1.f, sum) : 0.f;
#pragma unroll
            for (int nt = 0; nt < 14; nt++) {
                acc[nt][rr * 2] *= inv; acc[nt][rr * 2 + 1] *= inv;
            }
        }

        // ---- PV ----
        float oacc[4][4];
#pragma unroll
        for (int nt = 0; nt < 4; nt++)
#pragma unroll
            for (int i = 0; i < 4; i++) oacc[nt][i] = 0.f;

#pragma unroll
        for (int t = 0; t < 7; t++) {
            uint32_t ph[4], pl[4];
            ph[0] = pack_split(acc[2*t][0],   acc[2*t][1],   pl[0]);
            ph[1] = pack_split(acc[2*t][2],   acc[2*t][3],   pl[1]);
            ph[2] = pack_split(acc[2*t+1][0], acc[2*t+1][1], pl[2]);
            ph[3] = pack_split(acc[2*t+1][2], acc[2*t+1][3], pl[3]);
#pragma unroll
            for (int np = 0; np < 2; np++) {
                uint32_t boff = (uint32_t)((t * 16 + t_rp) * 136 + h * 32 + np * 16 + t_cs) * 2;
                uint32_t h0, h1, h2, h3, l0, l1, l2, l3;
                LDSM_X4_T(h0, h1, h2, h3, sbase + TVH + boff);
                LDSM_X4_T(l0, l1, l2, l3, sbase + TVL + boff);
                MMA_BF16(oacc[np * 2],     ph, h0, h1);
                MMA_BF16(oacc[np * 2],     pl, h0, h1);
                MMA_BF16(oacc[np * 2],     ph, l0, l1);
                MMA_BF16(oacc[np * 2 + 1], ph, h2, h3);
                MMA_BF16(oacc[np * 2 + 1], pl, h2, h3);
                MMA_BF16(oacc[np * 2 + 1], ph, l2, l3);
            }
        }

        // ---- store O pre-split ----
        const int n0 = mt * 16 + er;
#pragma unroll
        for (int nt = 0; nt < 4; nt++) {
            int ch = h * 32 + nt * 8 + ec;
            if (n0 < N_TOK) {
                uint32_t ul, uh = pack_split(oacc[nt][0], oacc[nt][1], ul);
                size_t off = ((size_t)b * N_TOK + n0) * 128 + ch;
                *(uint32_t*)&g_oh[off] = uh;
                *(uint32_t*)&g_ol[off] = ul;
            }
            if (n0 + 8 < N_TOK) {
                uint32_t ul, uh = pack_split(oacc[nt][2], oacc[nt][3], ul);
                size_t off = ((size_t)b * N_TOK + n0 + 8) * 128 + ch;
                *(uint32_t*)&g_oh[off] = uh;
                *(uint32_t*)&g_ol[off] = ul;
            }
        }
    }
}

// ======================= launch =======================
extern "C" void kernel_launch(void* const* d_in, const int* in_sizes, int n_in,
                              void* d_out, int out_size)
{
    const float* x          = (const float*)d_in[0];
    const float* mask       = (const float*)d_in[1];
    const float* qkv_w      = (const float*)d_in[2];
    const float* qkv_b      = (const float*)d_in[3];
    const float* proj_w     = (const float*)d_in[4];
    const float* proj_b     = (const float*)d_in[5];
    const float* bias_table = (const float*)d_in[6];
    const int*   rel_idx    = (const int*)d_in[7];
    float*       out        = (float*)d_out;

    const int B    = in_sizes[0] / (N_TOK * DIM);
    const int Mtot = B * N_TOK;
    const int mtiles = (Mtot + 127) / 128;

    __nv_bfloat16 *xh, *xl, *qwh, *qwl, *pwh, *pwl, *qkvh, *qkvl, *oh, *ol;
    cudaGetSymbolAddress((void**)&xh, g_xh);   cudaGetSymbolAddress((void**)&xl, g_xl);
    cudaGetSymbolAddress((void**)&qwh, g_qwh); cudaGetSymbolAddress((void**)&qwl, g_qwl);
    cudaGetSymbolAddress((void**)&pwh, g_pwh); cudaGetSymbolAddress((void**)&pwl, g_pwl);
    cudaGetSymbolAddress((void**)&qkvh, g_qkvh); cudaGetSymbolAddress((void**)&qkvl, g_qkvl);
    cudaGetSymbolAddress((void**)&oh, g_oh);   cudaGetSymbolAddress((void**)&ol, g_ol);

    cudaFuncSetAttribute(gemm_bf16x3<0>,
                         cudaFuncAttributeMaxDynamicSharedMemorySize, G_SMEM_BYTES);
    cudaFuncSetAttribute(gemm_bf16x3<1>,
                         cudaFuncAttributeMaxDynamicSharedMemorySize, G_SMEM_BYTES);
    cudaFuncSetAttribute(attn_kernel,
                         cudaFuncAttributeMaxDynamicSharedMemorySize, ATTN_SMEM);

    // prologue: pre-split x and weights, build comb
    {
        int n8 = Mtot * 128 / 8;
        split_kernel<<<(n8 + 255) / 256, 256>>>(x, xh, xl, n8);
        split_kernel<<<(384 * 128 / 8 + 255) / 256, 256>>>(qkv_w, qwh, qwl, 384 * 128 / 8);
        split_kernel<<<(128 * 128 / 8 + 255) / 256, 256>>>(proj_w, pwh, pwl, 128 * 128 / 8);
        const int total = NWIN * HEADS * N_TOK * N_TOK;
        comb_kernel<<<(total + 255) / 256, 256>>>(mask, bias_table, rel_idx);
    }
    gemm_bf16x3<0><<<dim3(mtiles, 3), 256, G_SMEM_BYTES>>>(
        xh, xl, qwh, qwl, qkv_b, qkvh, qkvl, nullptr, 384, Mtot);
    attn_kernel<<<B, 512, ATTN_SMEM>>>();
    gemm_bf16x3<1><<<dim3(mtiles, 1), 256, G_SMEM_BYTES>>>(
        oh, ol, pwh, pwl, proj_b, nullptr, nullptr, out, 128, Mtot);
}

// round 10
// speedup vs baseline: 1.0130x; 1.0130x over previous
#include <cuda_runtime.h>
#include <cuda_bf16.h>
#include <cstdint>

#define N_TOK 98
#define DIM   128
#define HEADS 4
#define NWIN  64
#define SCALE 0.17677669529663687f

#define MAX_B    2048
#define MAX_MTOT (MAX_B * N_TOK)

__device__ __nv_bfloat16 g_xh[(size_t)MAX_MTOT * 128];
__device__ __nv_bfloat16 g_xl[(size_t)MAX_MTOT * 128];
__device__ __nv_bfloat16 g_qwh[384 * 128];
__device__ __nv_bfloat16 g_qwl[384 * 128];
__device__ __nv_bfloat16 g_pwh[128 * 128];
__device__ __nv_bfloat16 g_pwl[128 * 128];
__device__ __nv_bfloat16 g_qkvh[(size_t)MAX_MTOT * 384];
__device__ __nv_bfloat16 g_qkvl[(size_t)MAX_MTOT * 384];
__device__ __nv_bfloat16 g_oh[(size_t)MAX_MTOT * 128];
__device__ __nv_bfloat16 g_ol[(size_t)MAX_MTOT * 128];
__device__ float g_comb[NWIN * HEADS * N_TOK * N_TOK];

// ======================= helpers =======================
static __device__ __forceinline__ uint32_t smem_u32(const void* p) {
    uint32_t a;
    asm("{ .reg .u64 t; cvta.to.shared.u64 t, %1; cvt.u32.u64 %0, t; }" : "=r"(a) : "l"(p));
    return a;
}
#define LDSM_X4(r0, r1, r2, r3, addr)                                          \
    asm volatile("ldmatrix.sync.aligned.m8n8.x4.shared.b16 {%0,%1,%2,%3}, [%4];" \
                 : "=r"(r0), "=r"(r1), "=r"(r2), "=r"(r3) : "r"(addr))
#define LDSM_X4_T(r0, r1, r2, r3, addr)                                        \
    asm volatile("ldmatrix.sync.aligned.m8n8.x4.trans.shared.b16 {%0,%1,%2,%3}, [%4];" \
                 : "=r"(r0), "=r"(r1), "=r"(r2), "=r"(r3) : "r"(addr))
#define MMA_BF16(c, a, b0, b1)                                                 \
    asm volatile("mma.sync.aligned.m16n8k16.row.col.f32.bf16.bf16.f32 "        \
                 "{%0,%1,%2,%3}, {%4,%5,%6,%7}, {%8,%9}, {%0,%1,%2,%3};"       \
                 : "+f"((c)[0]), "+f"((c)[1]), "+f"((c)[2]), "+f"((c)[3])      \
                 : "r"((a)[0]), "r"((a)[1]), "r"((a)[2]), "r"((a)[3]),         \
                   "r"(b0), "r"(b1))
#define CP_ASYNC16(dst, src)                                                   \
    asm volatile("cp.async.cg.shared.global [%0], [%1], 16;"                   \
                 :: "r"(dst), "l"(src))
#define CP_COMMIT() asm volatile("cp.async.commit_group;" ::: "memory")
#define CP_WAIT0()  asm volatile("cp.async.wait_group 0;" ::: "memory")

static __device__ __forceinline__ void bf16split(float a, __nv_bfloat16& h, __nv_bfloat16& l) {
    h = __float2bfloat16_rn(a);
    l = __float2bfloat16_rn(a - __bfloat162float(h));
}
static __device__ __forceinline__ uint32_t pack_split(float a, float b, uint32_t& lo) {
    __nv_bfloat16 ah, al, bh, bl;
    bf16split(a, ah, al); bf16split(b, bh, bl);
    uint16_t ahu = *(uint16_t*)&ah, alu = *(uint16_t*)&al;
    uint16_t bhu = *(uint16_t*)&bh, blu = *(uint16_t*)&bl;
    lo = ((uint32_t)blu << 16) | alu;
    return ((uint32_t)bhu << 16) | ahu;
}

extern __shared__ char smraw[];

// ======================= split prologue =======================
__global__ void split_kernel(const float* __restrict__ src,
                             __nv_bfloat16* __restrict__ h,
                             __nv_bfloat16* __restrict__ l, int n8)
{
    int i = blockIdx.x * 256 + threadIdx.x;
    if (i >= n8) return;
    const float4* s = (const float4*)src;
    float4 a = s[i * 2], b = s[i * 2 + 1];
    __nv_bfloat16 hh[8], ll[8];
    bf16split(a.x, hh[0], ll[0]); bf16split(a.y, hh[1], ll[1]);
    bf16split(a.z, hh[2], ll[2]); bf16split(a.w, hh[3], ll[3]);
    bf16split(b.x, hh[4], ll[4]); bf16split(b.y, hh[5], ll[5]);
    bf16split(b.z, hh[6], ll[6]); bf16split(b.w, hh[7], ll[7]);
    *(uint4*)&h[(size_t)i * 8] = *(uint4*)hh;
    *(uint4*)&l[(size_t)i * 8] = *(uint4*)ll;
}

// ======================= bf16x3 GEMM (R8 loop, pre-split operands) =======================
// smem: A hi/lo [128][136]; W hi/lo [128][72] (K-64 chunk)
#define AHI_  0
#define ALO_  34816
#define WHI_  69632
#define WLO_  88064
#define G_SMEM_BYTES 106496

template <int MODE>   // 0 = QKV (packed split bf16 out, scale on y==0), 1 = proj (fp32 out)
__global__ __launch_bounds__(256, 2)
void gemm_bf16x3(const __nv_bfloat16* __restrict__ Ah,
                 const __nv_bfloat16* __restrict__ Al,
                 const __nv_bfloat16* __restrict__ Wh,
                 const __nv_bfloat16* __restrict__ Wl,
                 const float* __restrict__ bias,
                 __nv_bfloat16* __restrict__ OutH,
                 __nv_bfloat16* __restrict__ OutL,
                 float* __restrict__ OutF,
                 int Nout, int Mtot)
{
    char* sb = smraw;
    const uint32_t sbase = smem_u32(sb);
    const int tid  = threadIdx.x;
    const int lane = tid & 31;
    const int warp = tid >> 5;
    const int wm   = warp & 3;
    const int wn   = warp >> 2;
    const long row0 = (long)blockIdx.x * 128;
    const int  col0 = blockIdx.y * 128;

    // ---- stage A [128 x 128] hi/lo: pure uint4 copies ----
#pragma unroll
    for (int jj = 0; jj < 16; jj++) {
        int lin = tid + jj * 256;          // 4096 = 2 arrays x 128 rows x 16 u4
        int arr = lin >> 11, rem = lin & 2047;
        int r = rem >> 4, u = rem & 15;
        long row = row0 + r;
        uint4 v = make_uint4(0u, 0u, 0u, 0u);
        if (row < Mtot)
            v = *((const uint4*)((arr ? Al : Ah) + row * 128) + u);
        *(uint4*)(sb + (arr ? ALO_ : AHI_) + r * 272 + u * 16) = v;
    }

    float acc[2][8][4];
#pragma unroll
    for (int mt = 0; mt < 2; mt++)
#pragma unroll
        for (int nt = 0; nt < 8; nt++)
#pragma unroll
            for (int i = 0; i < 4; i++) acc[mt][nt][i] = 0.f;

    const int a_row = wm * 32 + (lane & 15);
    const int a_cs  = (lane >> 4) * 8;
    const int b_i   = lane >> 3;
    const int b_rp  = (b_i >> 1) * 8 + (lane & 7);
    const int b_cs  = (b_i & 1) * 8;

#pragma unroll 1
    for (int kc = 0; kc < 2; kc++) {
        __syncthreads();
        // ---- stage W chunk [128 rows x 64 K] hi/lo: pure uint4 copies ----
#pragma unroll
        for (int jj = 0; jj < 8; jj++) {
            int lin = tid + jj * 256;      // 2048 = 2 arrays x 128 rows x 8 u4
            int arr = lin >> 10, rem = lin & 1023;
            int r = rem >> 3, u = rem & 7;
            uint4 v = *((const uint4*)((arr ? Wl : Wh) + (size_t)(col0 + r) * 128 + kc * 64) + u);
            *(uint4*)(sb + (arr ? WLO_ : WHI_) + r * 144 + u * 16) = v;
        }
        __syncthreads();

#pragma unroll
        for (int ks = 0; ks < 4; ks++) {
            uint32_t ah[2][4], al[2][4];
#pragma unroll
            for (int mt = 0; mt < 2; mt++) {
                uint32_t off = (uint32_t)((a_row + mt * 16) * 136 + kc * 64 + ks * 16 + a_cs) * 2;
                LDSM_X4(ah[mt][0], ah[mt][1], ah[mt][2], ah[mt][3], sbase + AHI_ + off);
                LDSM_X4(al[mt][0], al[mt][1], al[mt][2], al[mt][3], sbase + ALO_ + off);
            }
#pragma unroll
            for (int np = 0; np < 4; np++) {
                uint32_t off = (uint32_t)((wn * 64 + np * 16 + b_rp) * 72 + ks * 16 + b_cs) * 2;
                uint32_t h0, h1, h2, h3, l0, l1, l2, l3;
                LDSM_X4(h0, h1, h2, h3, sbase + WHI_ + off);
                LDSM_X4(l0, l1, l2, l3, sbase + WLO_ + off);
#pragma unroll
                for (int mt = 0; mt < 2; mt++) {
                    MMA_BF16(acc[mt][np * 2],     ah[mt], h0, h1);
                    MMA_BF16(acc[mt][np * 2],     al[mt], h0, h1);
                    MMA_BF16(acc[mt][np * 2],     ah[mt], l0, l1);
                    MMA_BF16(acc[mt][np * 2 + 1], ah[mt], h2, h3);
                    MMA_BF16(acc[mt][np * 2 + 1], al[mt], h2, h3);
                    MMA_BF16(acc[mt][np * 2 + 1], ah[mt], l2, l3);
                }
            }
        }
    }

    // ---- epilogue ----
    const int er = lane >> 2;
    const int ec = (lane & 3) * 2;
    const float osc = (MODE == 0 && blockIdx.y == 0) ? SCALE : 1.f;
#pragma unroll
    for (int mt = 0; mt < 2; mt++) {
        long r = row0 + wm * 32 + mt * 16 + er;
#pragma unroll
        for (int nt = 0; nt < 8; nt++) {
            int c = col0 + wn * 64 + nt * 8 + ec;
            float b0 = bias[c], b1 = bias[c + 1];
            if (MODE == 0) {
                if (r < Mtot) {
                    uint32_t ul, uh = pack_split((acc[mt][nt][0] + b0) * osc,
                                                 (acc[mt][nt][1] + b1) * osc, ul);
                    *(uint32_t*)&OutH[r * Nout + c] = uh;
                    *(uint32_t*)&OutL[r * Nout + c] = ul;
                }
                if (r + 8 < Mtot) {
                    uint32_t ul, uh = pack_split((acc[mt][nt][2] + b0) * osc,
                                                 (acc[mt][nt][3] + b1) * osc, ul);
                    *(uint32_t*)&OutH[(r + 8) * Nout + c] = uh;
                    *(uint32_t*)&OutL[(r + 8) * Nout + c] = ul;
                }
            } else {
                if (r < Mtot)
                    *(float2*)&OutF[r * Nout + c] =
                        make_float2(acc[mt][nt][0] + b0, acc[mt][nt][1] + b1);
                if (r + 8 < Mtot)
                    *(float2*)&OutF[(r + 8) * Nout + c] =
                        make_float2(acc[mt][nt][2] + b0, acc[mt][nt][3] + b1);
            }
        }
    }
}

// ======================= comb = bias_table[rel_idx] + mask =======================
__global__ void comb_kernel(const float* __restrict__ mask,
                            const float* __restrict__ bias_table,
                            const int*   __restrict__ rel_idx)
{
    int idx = blockIdx.x * blockDim.x + threadIdx.x;
    const int total = NWIN * HEADS * N_TOK * N_TOK;
    if (idx >= total) return;
    int w   = idx / (HEADS * N_TOK * N_TOK);
    int rem = idx - w * (HEADS * N_TOK * N_TOK);
    int h   = rem / (N_TOK * N_TOK);
    int nm  = rem - h * (N_TOK * N_TOK);
    g_comb[idx] = bias_table[rel_idx[nm] * HEADS + h] + mask[w * (N_TOK * N_TOK) + nm];
}

// ======================= attention: R8 core, cp.async pure-copy staging =======================
#define TQH 0
#define TQL 30464
#define TKH 60928
#define TKL 91392
#define TVH 121856
#define TVL 152320
#define ATTN_SMEM 182784

__global__ __launch_bounds__(512, 1)
void attn_kernel()
{
    char* sb = smraw;
    const uint32_t sbase = smem_u32(sb);
    const int b    = blockIdx.x;
    const int tid  = threadIdx.x;
    const int lane = tid & 31;
    const int warp = tid >> 5;
    const int win  = b & (NWIN - 1);

    // zero V pad rows 98..111 (hi/lo) — disjoint from cp.async region (rows 0..97)
    for (int i = tid; i < 14 * 68; i += 512) {
        int r = 98 + i / 68, c4 = (i % 68) * 2;
        *(uint32_t*)(sb + TVH + (r * 136 + c4) * 2) = 0u;
        *(uint32_t*)(sb + TVL + (r * 136 + c4) * 2) = 0u;
    }

    // ---- stage Q/K/V hi/lo via cp.async 16B pure copies ----
    {
        const __nv_bfloat16* qh = g_qkvh + (size_t)b * N_TOK * 384;
        const __nv_bfloat16* ql = g_qkvl + (size_t)b * N_TOK * 384;
        for (int i = tid; i < N_TOK * 16; i += 512) {
            int m = i >> 4, u = i & 15;                 // row, uint4 within 128-elem segment
            int so = m * 384 + u * 8;                   // elements
            uint32_t dq = (uint32_t)(m * 272 + u * 16); // bytes
            CP_ASYNC16(sbase + TQH + dq, qh + so);
            CP_ASYNC16(sbase + TQL + dq, ql + so);
            CP_ASYNC16(sbase + TKH + dq, qh + so + 128);
            CP_ASYNC16(sbase + TKL + dq, ql + so + 128);
            CP_ASYNC16(sbase + TVH + dq, qh + so + 256);
            CP_ASYNC16(sbase + TVL + dq, ql + so + 256);
        }
        CP_COMMIT();
        CP_WAIT0();
    }
    __syncthreads();

    const int a_rp = lane & 15;
    const int a_cs = (lane >> 4) * 8;
    const int b_i  = lane >> 3;
    const int b_rp = (b_i >> 1) * 8 + (lane & 7);
    const int b_cs = (b_i & 1) * 8;
    const int t_rp = (b_i & 1) * 8 + (lane & 7);
    const int t_cs = (b_i >> 1) * 8;
    const int er   = lane >> 2;
    const int ec   = (lane & 3) * 2;

#pragma unroll 1
    for (int item = warp; item < 28; item += 16) {
        const int h  = item / 7;
        const int mt = item - h * 7;

        // ---- QK^T ----
        float acc[14][4];
#pragma unroll
        for (int nt = 0; nt < 14; nt++)
#pragma unroll
            for (int i = 0; i < 4; i++) acc[nt][i] = 0.f;

#pragma unroll
        for (int ks = 0; ks < 2; ks++) {
            const int kb = h * 32 + ks * 16;
            uint32_t ah[4], al[4];
            uint32_t aoff = (uint32_t)((mt * 16 + a_rp) * 136 + kb + a_cs) * 2;
            LDSM_X4(ah[0], ah[1], ah[2], ah[3], sbase + TQH + aoff);
            LDSM_X4(al[0], al[1], al[2], al[3], sbase + TQL + aoff);
#pragma unroll
            for (int np = 0; np < 7; np++) {
                uint32_t boff = (uint32_t)((np * 16 + b_rp) * 136 + kb + b_cs) * 2;
                uint32_t h0, h1, h2, h3, l0, l1, l2, l3;
                LDSM_X4(h0, h1, h2, h3, sbase + TKH + boff);
                LDSM_X4(l0, l1, l2, l3, sbase + TKL + boff);
                MMA_BF16(acc[np * 2],     ah, h0, h1);
                MMA_BF16(acc[np * 2],     al, h0, h1);
                MMA_BF16(acc[np * 2],     ah, l0, l1);
                MMA_BF16(acc[np * 2 + 1], ah, h2, h3);
                MMA_BF16(acc[np * 2 + 1], al, h2, h3);
                MMA_BF16(acc[np * 2 + 1], ah, l2, l3);
            }
        }

        // ---- softmax in registers ----
        const float* combh = g_comb + (size_t)(win * HEADS + h) * N_TOK * N_TOK;
#pragma unroll
        for (int rr = 0; rr < 2; rr++) {
            int n = mt * 16 + er + rr * 8;
            bool rowok = (n < N_TOK);
            int  nc = rowok ? n : 0;
            float mx = -1e30f;
#pragma unroll
            for (int nt = 0; nt < 14; nt++) {
                int m = nt * 8 + ec;
                float v0 = -1e30f, v1 = -1e30f;
                if (m < N_TOK) {
                    float2 cb = *(const float2*)&combh[nc * N_TOK + m];
                    v0 = acc[nt][rr * 2]     + cb.x;
                    v1 = acc[nt][rr * 2 + 1] + cb.y;
                }
                acc[nt][rr * 2] = v0; acc[nt][rr * 2 + 1] = v1;
                mx = fmaxf(mx, fmaxf(v0, v1));
            }
            mx = fmaxf(mx, __shfl_xor_sync(0xffffffffu, mx, 1));
            mx = fmaxf(mx, __shfl_xor_sync(0xffffffffu, mx, 2));
            float sum = 0.f;
#pragma unroll
            for (int nt = 0; nt < 14; nt++) {
                float e0 = __expf(acc[nt][rr * 2]     - mx);
                float e1 = __expf(acc[nt][rr * 2 + 1] - mx);
                acc[nt][rr * 2] = e0; acc[nt][rr * 2 + 1] = e1;
                sum += e0 + e1;
            }
            sum += __shfl_xor_sync(0xffffffffu, sum, 1);
            sum += __shfl_xor_sync(0xffffffffu, sum, 2);
            float inv = rowok ? __fdividef(1.f, sum) : 0.f;
#pragma unroll
            for (int nt = 0; nt < 14; nt++) {
                acc[nt][rr * 2] *= inv; acc[nt][rr * 2 + 1] *= inv;
            }
        }

        // ---- PV ----
        float oacc[4][4];
#pragma unroll
        for (int nt = 0; nt < 4; nt++)
#pragma unroll
            for (int i = 0; i < 4; i++) oacc[nt][i] = 0.f;

#pragma unroll
        for (int t = 0; t < 7; t++) {
            uint32_t ph[4], pl[4];
            ph[0] = pack_split(acc[2*t][0],   acc[2*t][1],   pl[0]);
            ph[1] = pack_split(acc[2*t][2],   acc[2*t][3],   pl[1]);
            ph[2] = pack_split(acc[2*t+1][0], acc[2*t+1][1], pl[2]);
            ph[3] = pack_split(acc[2*t+1][2], acc[2*t+1][3], pl[3]);
#pragma unroll
            for (int np = 0; np < 2; np++) {
                uint32_t boff = (uint32_t)((t * 16 + t_rp) * 136 + h * 32 + np * 16 + t_cs) * 2;
                uint32_t h0, h1, h2, h3, l0, l1, l2, l3;
                LDSM_X4_T(h0, h1, h2, h3, sbase + TVH + boff);
                LDSM_X4_T(l0, l1, l2, l3, sbase + TVL + boff);
                MMA_BF16(oacc[np * 2],     ph, h0, h1);
                MMA_BF16(oacc[np * 2],     pl, h0, h1);
                MMA_BF16(oacc[np * 2],     ph, l0, l1);
                MMA_BF16(oacc[np * 2 + 1], ph, h2, h3);
                MMA_BF16(oacc[np * 2 + 1], pl, h2, h3);
                MMA_BF16(oacc[np * 2 + 1], ph, l2, l3);
            }
        }

        // ---- store O pre-split ----
        const int n0 = mt * 16 + er;
#pragma unroll
        for (int nt = 0; nt < 4; nt++) {
            int ch = h * 32 + nt * 8 + ec;
            if (n0 < N_TOK) {
                uint32_t ul, uh = pack_split(oacc[nt][0], oacc[nt][1], ul);
                size_t off = ((size_t)b * N_TOK + n0) * 128 + ch;
                *(uint32_t*)&g_oh[off] = uh;
                *(uint32_t*)&g_ol[off] = ul;
            }
            if (n0 + 8 < N_TOK) {
                uint32_t ul, uh = pack_split(oacc[nt][2], oacc[nt][3], ul);
                size_t off = ((size_t)b * N_TOK + n0 + 8) * 128 + ch;
                *(uint32_t*)&g_oh[off] = uh;
                *(uint32_t*)&g_ol[off] = ul;
            }
        }
    }
}

// ======================= launch =======================
extern "C" void kernel_launch(void* const* d_in, const int* in_sizes, int n_in,
                              void* d_out, int out_size)
{
    const float* x          = (const float*)d_in[0];
    const float* mask       = (const float*)d_in[1];
    const float* qkv_w      = (const float*)d_in[2];
    const float* qkv_b      = (const float*)d_in[3];
    const float* proj_w     = (const float*)d_in[4];
    const float* proj_b     = (const float*)d_in[5];
    const float* bias_table = (const float*)d_in[6];
    const int*   rel_idx    = (const int*)d_in[7];
    float*       out        = (float*)d_out;

    const int B    = in_sizes[0] / (N_TOK * DIM);
    const int Mtot = B * N_TOK;
    const int mtiles = (Mtot + 127) / 128;

    __nv_bfloat16 *xh, *xl, *qwh, *qwl, *pwh, *pwl, *qkvh, *qkvl, *oh, *ol;
    cudaGetSymbolAddress((void**)&xh, g_xh);   cudaGetSymbolAddress((void**)&xl, g_xl);
    cudaGetSymbolAddress((void**)&qwh, g_qwh); cudaGetSymbolAddress((void**)&qwl, g_qwl);
    cudaGetSymbolAddress((void**)&pwh, g_pwh); cudaGetSymbolAddress((void**)&pwl, g_pwl);
    cudaGetSymbolAddress((void**)&qkvh, g_qkvh); cudaGetSymbolAddress((void**)&qkvl, g_qkvl);
    cudaGetSymbolAddress((void**)&oh, g_oh);   cudaGetSymbolAddress((void**)&ol, g_ol);

    cudaFuncSetAttribute(gemm_bf16x3<0>,
                         cudaFuncAttributeMaxDynamicSharedMemorySize, G_SMEM_BYTES);
    cudaFuncSetAttribute(gemm_bf16x3<1>,
                         cudaFuncAttributeMaxDynamicSharedMemorySize, G_SMEM_BYTES);
    cudaFuncSetAttribute(attn_kernel,
                         cudaFuncAttributeMaxDynamicSharedMemorySize, ATTN_SMEM);

    {
        int n8 = Mtot * 128 / 8;
        split_kernel<<<(n8 + 255) / 256, 256>>>(x, xh, xl, n8);
        split_kernel<<<(384 * 128 / 8 + 255) / 256, 256>>>(qkv_w, qwh, qwl, 384 * 128 / 8);
        split_kernel<<<(128 * 128 / 8 + 255) / 256, 256>>>(proj_w, pwh, pwl, 128 * 128 / 8);
        const int total = NWIN * HEADS * N_TOK * N_TOK;
        comb_kernel<<<(total + 255) / 256, 256>>>(mask, bias_table, rel_idx);
    }
    gemm_bf16x3<0><<<dim3(mtiles, 3), 256, G_SMEM_BYTES>>>(
        xh, xl, qwh, qwl, qkv_b, qkvh, qkvl, nullptr, 384, Mtot);
    attn_kernel<<<B, 512, ATTN_SMEM>>>();
    gemm_bf16x3<1><<<dim3(mtiles, 1), 256, G_SMEM_BYTES>>>(
        oh, ol, pwh, pwl, proj_b, nullptr, nullptr, out, 128, Mtot);
}

// round 11
// speedup vs baseline: 1.1394x; 1.1248x over previous
#include <cuda_runtime.h>
#include <cuda_bf16.h>
#include <cstdint>

#define N_TOK 98
#define DIM   128
#define HEADS 4
#define NWIN  64
#define SCALE 0.17677669529663687f

#define MAX_B    2048
#define MAX_MTOT (MAX_B * N_TOK)

__device__ float g_qkv[(size_t)MAX_MTOT * 384];
__device__ float g_o[(size_t)MAX_MTOT * 128];
__device__ float g_comb[NWIN * HEADS * N_TOK * N_TOK];

// ======================= helpers =======================
static __device__ __forceinline__ uint32_t smem_u32(const void* p) {
    uint32_t a;
    asm("{ .reg .u64 t; cvta.to.shared.u64 t, %1; cvt.u32.u64 %0, t; }" : "=r"(a) : "l"(p));
    return a;
}
#define LDSM_X4(r0, r1, r2, r3, addr)                                          \
    asm volatile("ldmatrix.sync.aligned.m8n8.x4.shared.b16 {%0,%1,%2,%3}, [%4];" \
                 : "=r"(r0), "=r"(r1), "=r"(r2), "=r"(r3) : "r"(addr))
#define LDSM_X4_T(r0, r1, r2, r3, addr)                                        \
    asm volatile("ldmatrix.sync.aligned.m8n8.x4.trans.shared.b16 {%0,%1,%2,%3}, [%4];" \
                 : "=r"(r0), "=r"(r1), "=r"(r2), "=r"(r3) : "r"(addr))
#define MMA_BF16(c, a, b0, b1)                                                 \
    asm volatile("mma.sync.aligned.m16n8k16.row.col.f32.bf16.bf16.f32 "        \
                 "{%0,%1,%2,%3}, {%4,%5,%6,%7}, {%8,%9}, {%0,%1,%2,%3};"       \
                 : "+f"((c)[0]), "+f"((c)[1]), "+f"((c)[2]), "+f"((c)[3])      \
                 : "r"((a)[0]), "r"((a)[1]), "r"((a)[2]), "r"((a)[3]),         \
                   "r"(b0), "r"(b1))

static __device__ __forceinline__ void bf16split(float a, __nv_bfloat16& h, __nv_bfloat16& l) {
    h = __float2bfloat16_rn(a);
    l = __float2bfloat16_rn(a - __bfloat162float(h));
}
static __device__ __forceinline__ uint32_t pack_split(float a, float b, uint32_t& lo) {
    __nv_bfloat16 ah, al, bh, bl;
    bf16split(a, ah, al); bf16split(b, bh, bl);
    uint16_t ahu = *(uint16_t*)&ah, alu = *(uint16_t*)&al;
    uint16_t bhu = *(uint16_t*)&bh, blu = *(uint16_t*)&bl;
    lo = ((uint32_t)blu << 16) | alu;
    return ((uint32_t)bhu << 16) | ahu;
}

extern __shared__ char smraw[];

// ======================= bf16x3 GEMM: Out[M,N] = A[M,128] @ W[N,128]^T + bias ====================
// R8 loop, with in-kernel nc loop over 128-col W slabs (A staged ONCE per block).
#define G_AHI 0
#define G_ALO 34816
#define G_WHI 69632
#define G_WLO 88064
#define G_SMEM_BYTES 106496

__global__ __launch_bounds__(256, 2)
void gemm_bf16x3(const float* __restrict__ A,
                 const float* __restrict__ W,
                 const float* __restrict__ bias,
                 float* __restrict__ Out,
                 int Nout, int Mtot, int Ntiles)
{
    __nv_bfloat16* sb = (__nv_bfloat16*)smraw;
    const uint32_t sbase = smem_u32(sb);
    const int tid  = threadIdx.x;
    const int lane = tid & 31;
    const int warp = tid >> 5;
    const int wm   = warp & 3;
    const int wn   = warp >> 2;
    const long row0 = (long)blockIdx.x * 128;

    // ---- stage A [128 x 128] -> hi/lo bf16, stride 136 (once per block) ----
#pragma unroll 4
    for (int jj = 0; jj < 16; jj++) {
        int lin = tid + jj * 256;
        int r = lin >> 5, c = (lin & 31) * 4;
        float4 v = make_float4(0.f, 0.f, 0.f, 0.f);
        if (row0 + r < Mtot) v = *(const float4*)&A[(row0 + r) * 128 + c];
        __nv_bfloat16 h0, l0, h1, l1, h2, l2, h3, l3;
        bf16split(v.x, h0, l0); bf16split(v.y, h1, l1);
        bf16split(v.z, h2, l2); bf16split(v.w, h3, l3);
        int o = r * 136 + c;
        sb[(G_AHI>>1) + o] = h0; sb[(G_AHI>>1) + o + 1] = h1; sb[(G_AHI>>1) + o + 2] = h2; sb[(G_AHI>>1) + o + 3] = h3;
        sb[(G_ALO>>1) + o] = l0; sb[(G_ALO>>1) + o + 1] = l1; sb[(G_ALO>>1) + o + 2] = l2; sb[(G_ALO>>1) + o + 3] = l3;
    }

    const int a_row = wm * 32 + (lane & 15);
    const int a_cs  = (lane >> 4) * 8;
    const int b_i   = lane >> 3;
    const int b_rp  = (b_i >> 1) * 8 + (lane & 7);
    const int b_cs  = (b_i & 1) * 8;
    const int er = lane >> 2;
    const int ec = (lane & 3) * 2;

#pragma unroll 1
    for (int nc = 0; nc < Ntiles; nc++) {
        const int col0 = nc * 128;

        float acc[2][8][4];
#pragma unroll
        for (int mt = 0; mt < 2; mt++)
#pragma unroll
            for (int nt = 0; nt < 8; nt++)
#pragma unroll
                for (int i = 0; i < 4; i++) acc[mt][nt][i] = 0.f;

#pragma unroll 1
        for (int kc = 0; kc < 2; kc++) {
            __syncthreads();
            // ---- stage W chunk [128 rows x 64 K] -> hi/lo, stride 72 ----
#pragma unroll
            for (int jj = 0; jj < 8; jj++) {
                int lin = tid + jj * 256;
                int r = lin >> 4, c = (lin & 15) * 4;
                float4 v = *(const float4*)&W[(size_t)(col0 + r) * 128 + kc * 64 + c];
                __nv_bfloat16 h0, l0, h1, l1, h2, l2, h3, l3;
                bf16split(v.x, h0, l0); bf16split(v.y, h1, l1);
                bf16split(v.z, h2, l2); bf16split(v.w, h3, l3);
                int o = r * 72 + c;
                sb[(G_WHI>>1) + o] = h0; sb[(G_WHI>>1) + o + 1] = h1; sb[(G_WHI>>1) + o + 2] = h2; sb[(G_WHI>>1) + o + 3] = h3;
                sb[(G_WLO>>1) + o] = l0; sb[(G_WLO>>1) + o + 1] = l1; sb[(G_WLO>>1) + o + 2] = l2; sb[(G_WLO>>1) + o + 3] = l3;
            }
            __syncthreads();

#pragma unroll
            for (int ks = 0; ks < 4; ks++) {
                uint32_t ah[2][4], al[2][4];
#pragma unroll
                for (int mt = 0; mt < 2; mt++) {
                    uint32_t off = (uint32_t)((a_row + mt * 16) * 136 + kc * 64 + ks * 16 + a_cs) * 2;
                    LDSM_X4(ah[mt][0], ah[mt][1], ah[mt][2], ah[mt][3], sbase + G_AHI + off);
                    LDSM_X4(al[mt][0], al[mt][1], al[mt][2], al[mt][3], sbase + G_ALO + off);
                }
#pragma unroll
                for (int np = 0; np < 4; np++) {
                    uint32_t off = (uint32_t)((wn * 64 + np * 16 + b_rp) * 72 + ks * 16 + b_cs) * 2;
                    uint32_t h0, h1, h2, h3, l0, l1, l2, l3;
                    LDSM_X4(h0, h1, h2, h3, sbase + G_WHI + off);
                    LDSM_X4(l0, l1, l2, l3, sbase + G_WLO + off);
#pragma unroll
                    for (int mt = 0; mt < 2; mt++) {
                        MMA_BF16(acc[mt][np * 2],     ah[mt], h0, h1);
                        MMA_BF16(acc[mt][np * 2],     al[mt], h0, h1);
                        MMA_BF16(acc[mt][np * 2],     ah[mt], l0, l1);
                        MMA_BF16(acc[mt][np * 2 + 1], ah[mt], h2, h3);
                        MMA_BF16(acc[mt][np * 2 + 1], al[mt], h2, h3);
                        MMA_BF16(acc[mt][np * 2 + 1], ah[mt], l2, l3);
                    }
                }
            }
        }

        // ---- epilogue for this slab (registers + gmem only; no smem hazard) ----
#pragma unroll
        for (int mt = 0; mt < 2; mt++) {
            long r = row0 + wm * 32 + mt * 16 + er;
#pragma unroll
            for (int nt = 0; nt < 8; nt++) {
                int c = col0 + wn * 64 + nt * 8 + ec;
                float b0 = bias[c], b1 = bias[c + 1];
                if (r < Mtot)
                    *(float2*)&Out[r * Nout + c] =
                        make_float2(acc[mt][nt][0] + b0, acc[mt][nt][1] + b1);
                if (r + 8 < Mtot)
                    *(float2*)&Out[(r + 8) * Nout + c] =
                        make_float2(acc[mt][nt][2] + b0, acc[mt][nt][3] + b1);
            }
        }
    }
}

// ======================= comb = bias_table[rel_idx] + mask =======================
__global__ void comb_kernel(const float* __restrict__ mask,
                            const float* __restrict__ bias_table,
                            const int*   __restrict__ rel_idx)
{
    int idx = blockIdx.x * blockDim.x + threadIdx.x;
    const int total = NWIN * HEADS * N_TOK * N_TOK;
    if (idx >= total) return;
    int w   = idx / (HEADS * N_TOK * N_TOK);
    int rem = idx - w * (HEADS * N_TOK * N_TOK);
    int h   = rem / (N_TOK * N_TOK);
    int nm  = rem - h * (N_TOK * N_TOK);
    g_comb[idx] = bias_table[rel_idx[nm] * HEADS + h] + mask[w * (N_TOK * N_TOK) + nm];
}

// ======================= attention: R8 register flash (verbatim) =======================
#define TQH 0
#define TQL 30464
#define TKH 60928
#define TKL 91392
#define TVH 121856
#define TVL 152320
#define ATTN_SMEM 182784

__global__ __launch_bounds__(512, 1)
void attn_kernel()
{
    char* sb = smraw;
    const uint32_t sbase = smem_u32(sb);
    const int b    = blockIdx.x;
    const int tid  = threadIdx.x;
    const int lane = tid & 31;
    const int warp = tid >> 5;
    const int win  = b & (NWIN - 1);

    // zero V pad rows 98..111 (hi/lo)
    for (int i = tid; i < 14 * 68; i += 512) {
        int r = 98 + i / 68, c4 = (i % 68) * 2;
        *(uint32_t*)(sb + TVH + (r * 136 + c4) * 2) = 0u;
        *(uint32_t*)(sb + TVL + (r * 136 + c4) * 2) = 0u;
    }

    // ---- stage Q (scaled), K, V row-major bf16 hi/lo ----
    {
        const float* qk = g_qkv + (size_t)b * N_TOK * 384;
        for (int i = tid; i < N_TOK * 32; i += 512) {
            int m = i >> 5, c = (i & 31) * 4;
            const float* rp = qk + m * 384 + c;
            float4 q = *(const float4*)rp;
            float4 k = *(const float4*)(rp + 128);
            float4 v = *(const float4*)(rp + 256);
            q.x *= SCALE; q.y *= SCALE; q.z *= SCALE; q.w *= SCALE;
            __nv_bfloat16 hh[4], ll[4];
            bf16split(q.x, hh[0], ll[0]); bf16split(q.y, hh[1], ll[1]);
            bf16split(q.z, hh[2], ll[2]); bf16split(q.w, hh[3], ll[3]);
            *(uint2*)(sb + TQH + (m * 136 + c) * 2) = *(uint2*)hh;
            *(uint2*)(sb + TQL + (m * 136 + c) * 2) = *(uint2*)ll;
            bf16split(k.x, hh[0], ll[0]); bf16split(k.y, hh[1], ll[1]);
            bf16split(k.z, hh[2], ll[2]); bf16split(k.w, hh[3], ll[3]);
            *(uint2*)(sb + TKH + (m * 136 + c) * 2) = *(uint2*)hh;
            *(uint2*)(sb + TKL + (m * 136 + c) * 2) = *(uint2*)ll;
            bf16split(v.x, hh[0], ll[0]); bf16split(v.y, hh[1], ll[1]);
            bf16split(v.z, hh[2], ll[2]); bf16split(v.w, hh[3], ll[3]);
            *(uint2*)(sb + TVH + (m * 136 + c) * 2) = *(uint2*)hh;
            *(uint2*)(sb + TVL + (m * 136 + c) * 2) = *(uint2*)ll;
        }
    }
    __syncthreads();

    const int a_rp = lane & 15;
    const int a_cs = (lane >> 4) * 8;
    const int b_i  = lane >> 3;
    const int b_rp = (b_i >> 1) * 8 + (lane & 7);
    const int b_cs = (b_i & 1) * 8;
    const int t_rp = (b_i & 1) * 8 + (lane & 7);
    const int t_cs = (b_i >> 1) * 8;
    const int er   = lane >> 2;
    const int ec   = (lane & 3) * 2;

#pragma unroll 1
    for (int item = warp; item < 28; item += 16) {
        const int h  = item / 7;
        const int mt = item - h * 7;

        // ---- QK^T ----
        float acc[14][4];
#pragma unroll
        for (int nt = 0; nt < 14; nt++)
#pragma unroll
            for (int i = 0; i < 4; i++) acc[nt][i] = 0.f;

#pragma unroll
        for (int ks = 0; ks < 2; ks++) {
            const int kb = h * 32 + ks * 16;
            uint32_t ah[4], al[4];
            uint32_t aoff = (uint32_t)((mt * 16 + a_rp) * 136 + kb + a_cs) * 2;
            LDSM_X4(ah[0], ah[1], ah[2], ah[3], sbase + TQH + aoff);
            LDSM_X4(al[0], al[1], al[2], al[3], sbase + TQL + aoff);
#pragma unroll
            for (int np = 0; np < 7; np++) {
                uint32_t boff = (uint32_t)((np * 16 + b_rp) * 136 + kb + b_cs) * 2;
                uint32_t h0, h1, h2, h3, l0, l1, l2, l3;
                LDSM_X4(h0, h1, h2, h3, sbase + TKH + boff);
                LDSM_X4(l0, l1, l2, l3, sbase + TKL + boff);
                MMA_BF16(acc[np * 2],     ah, h0, h1);
                MMA_BF16(acc[np * 2],     al, h0, h1);
                MMA_BF16(acc[np * 2],     ah, l0, l1);
                MMA_BF16(acc[np * 2 + 1], ah, h2, h3);
                MMA_BF16(acc[np * 2 + 1], al, h2, h3);
                MMA_BF16(acc[np * 2 + 1], ah, l2, l3);
            }
        }

        // ---- softmax in registers ----
        const float* combh = g_comb + (size_t)(win * HEADS + h) * N_TOK * N_TOK;
#pragma unroll
        for (int rr = 0; rr < 2; rr++) {
            int n = mt * 16 + er + rr * 8;
            bool rowok = (n < N_TOK);
            int  nc = rowok ? n : 0;
            float mx = -1e30f;
#pragma unroll
            for (int nt = 0; nt < 14; nt++) {
                int m = nt * 8 + ec;
                float v0 = -1e30f, v1 = -1e30f;
                if (m < N_TOK) {
                    float2 cb = *(const float2*)&combh[nc * N_TOK + m];
                    v0 = acc[nt][rr * 2]     + cb.x;
                    v1 = acc[nt][rr * 2 + 1] + cb.y;
                }
                acc[nt][rr * 2] = v0; acc[nt][rr * 2 + 1] = v1;
                mx = fmaxf(mx, fmaxf(v0, v1));
            }
            mx = fmaxf(mx, __shfl_xor_sync(0xffffffffu, mx, 1));
            mx = fmaxf(mx, __shfl_xor_sync(0xffffffffu, mx, 2));
            float sum = 0.f;
#pragma unroll
            for (int nt = 0; nt < 14; nt++) {
                float e0 = __expf(acc[nt][rr * 2]     - mx);
                float e1 = __expf(acc[nt][rr * 2 + 1] - mx);
                acc[nt][rr * 2] = e0; acc[nt][rr * 2 + 1] = e1;
                sum += e0 + e1;
            }
            sum += __shfl_xor_sync(0xffffffffu, sum, 1);
            sum += __shfl_xor_sync(0xffffffffu, sum, 2);
            float inv = rowok ? __fdividef(1.f, sum) : 0.f;
#pragma unroll
            for (int nt = 0; nt < 14; nt++) {
                acc[nt][rr * 2] *= inv; acc[nt][rr * 2 + 1] *= inv;
            }
        }

        // ---- PV: P in registers, V via ldmatrix.trans ----
        float oacc[4][4];
#pragma unroll
        for (int nt = 0; nt < 4; nt++)
#pragma unroll
            for (int i = 0; i < 4; i++) oacc[nt][i] = 0.f;

#pragma unroll
        for (int t = 0; t < 7; t++) {
            uint32_t ph[4], pl[4];
            ph[0] = pack_split(acc[2*t][0],   acc[2*t][1],   pl[0]);
            ph[1] = pack_split(acc[2*t][2],   acc[2*t][3],   pl[1]);
            ph[2] = pack_split(acc[2*t+1][0], acc[2*t+1][1], pl[2]);
            ph[3] = pack_split(acc[2*t+1][2], acc[2*t+1][3], pl[3]);
#pragma unroll
            for (int np = 0; np < 2; np++) {
                uint32_t boff = (uint32_t)((t * 16 + t_rp) * 136 + h * 32 + np * 16 + t_cs) * 2;
                uint32_t h0, h1, h2, h3, l0, l1, l2, l3;
                LDSM_X4_T(h0, h1, h2, h3, sbase + TVH + boff);
                LDSM_X4_T(l0, l1, l2, l3, sbase + TVL + boff);
                MMA_BF16(oacc[np * 2],     ph, h0, h1);
                MMA_BF16(oacc[np * 2],     pl, h0, h1);
                MMA_BF16(oacc[np * 2],     ph, l0, l1);
                MMA_BF16(oacc[np * 2 + 1], ph, h2, h3);
                MMA_BF16(oacc[np * 2 + 1], pl, h2, h3);
                MMA_BF16(oacc[np * 2 + 1], ph, l2, l3);
            }
        }

        // ---- store O ----
        const int n0 = mt * 16 + er;
#pragma unroll
        for (int nt = 0; nt < 4; nt++) {
            int ch = h * 32 + nt * 8 + ec;
            if (n0 < N_TOK)
                *(float2*)&g_o[((size_t)b * N_TOK + n0) * 128 + ch] =
                    make_float2(oacc[nt][0], oacc[nt][1]);
            if (n0 + 8 < N_TOK)
                *(float2*)&g_o[((size_t)b * N_TOK + n0 + 8) * 128 + ch] =
                    make_float2(oacc[nt][2], oacc[nt][3]);
        }
    }
}

// ======================= launch =======================
extern "C" void kernel_launch(void* const* d_in, const int* in_sizes, int n_in,
                              void* d_out, int out_size)
{
    const float* x          = (const float*)d_in[0];
    const float* mask       = (const float*)d_in[1];
    const float* qkv_w      = (const float*)d_in[2];
    const float* qkv_b      = (const float*)d_in[3];
    const float* proj_w     = (const float*)d_in[4];
    const float* proj_b     = (const float*)d_in[5];
    const float* bias_table = (const float*)d_in[6];
    const int*   rel_idx    = (const int*)d_in[7];
    float*       out        = (float*)d_out;

    const int B    = in_sizes[0] / (N_TOK * DIM);
    const int Mtot = B * N_TOK;
    const int mtiles = (Mtot + 127) / 128;

    float *qkv_ptr, *o_ptr;
    cudaGetSymbolAddress((void**)&qkv_ptr, g_qkv);
    cudaGetSymbolAddress((void**)&o_ptr, g_o);

    cudaFuncSetAttribute(gemm_bf16x3,
                         cudaFuncAttributeMaxDynamicSharedMemorySize, G_SMEM_BYTES);
    cudaFuncSetAttribute(attn_kernel,
                         cudaFuncAttributeMaxDynamicSharedMemorySize, ATTN_SMEM);

    {
        const int total = NWIN * HEADS * N_TOK * N_TOK;
        comb_kernel<<<(total + 255) / 256, 256>>>(mask, bias_table, rel_idx);
    }
    gemm_bf16x3<<<mtiles, 256, G_SMEM_BYTES>>>(x, qkv_w, qkv_b, qkv_ptr, 384, Mtot, 3);
    attn_kernel<<<B, 512, ATTN_SMEM>>>();
    gemm_bf16x3<<<mtiles, 256, G_SMEM_BYTES>>>(o_ptr, proj_w, proj_b, out, 128, Mtot, 1);
}